// round 1
// baseline (speedup 1.0000x reference)
#include <cuda_runtime.h>
#include <cuda_bf16.h>
#include <math.h>

// Problem constants
#define Nn 50000
#define Ee 800000
#define Gg 1000
#define ND 128
#define HH 256
#define LL 4
#define PP 3
#define H4 (HH/4)

// ---------------- static scratch (no allocations allowed) ----------------
__device__ float g_hA[Nn * HH];
__device__ float g_hB[Nn * HH];
__device__ float g_m[Nn * HH];
__device__ int   g_cnt[Nn];
__device__ int   g_fill[Nn];
__device__ float g_dinv[Nn];
__device__ int   g_rowptr[Nn + 1];
__device__ int   g_colidx[Ee];
__device__ float g_ew[Ee];
__device__ float g_pool[Gg * HH];

// ---------------- graph preprocessing ----------------
__global__ void k_zero()
{
    int i = blockIdx.x * blockDim.x + threadIdx.x;
    if (i < Nn) { g_cnt[i] = 0; g_fill[i] = 0; }
}

__global__ void k_count(const int* __restrict__ ei)
{
    int e = blockIdx.x * blockDim.x + threadIdx.x;
    if (e < Ee) atomicAdd(&g_cnt[ei[Ee + e]], 1);
}

__global__ void k_dinv()
{
    int i = blockIdx.x * blockDim.x + threadIdx.x;
    if (i < Nn) g_dinv[i] = rsqrtf(1.0f + (float)g_cnt[i]);
}

// single-block exclusive scan of g_cnt -> g_rowptr
__global__ void k_scan()
{
    __shared__ int sh[1024];
    __shared__ int carry;
    int t = threadIdx.x;
    if (t == 0) carry = 0;
    __syncthreads();
    for (int base = 0; base < Nn; base += 1024) {
        int i = base + t;
        int v = (i < Nn) ? g_cnt[i] : 0;
        sh[t] = v;
        __syncthreads();
        #pragma unroll
        for (int d = 1; d < 1024; d <<= 1) {
            int tv = (t >= d) ? sh[t - d] : 0;
            __syncthreads();
            sh[t] += tv;
            __syncthreads();
        }
        if (i < Nn) g_rowptr[i] = carry + sh[t] - v;   // exclusive
        int total = sh[1023];
        __syncthreads();
        if (t == 0) carry += total;
        __syncthreads();
    }
    if (t == 0) g_rowptr[Nn] = Ee;
}

__global__ void k_fill(const int* __restrict__ ei)
{
    int e = blockIdx.x * blockDim.x + threadIdx.x;
    if (e >= Ee) return;
    int s = ei[e];
    int d = ei[Ee + e];
    int pos = g_rowptr[d] + atomicAdd(&g_fill[d], 1);
    g_colidx[pos] = s;
    g_ew[pos] = g_dinv[s] * g_dinv[d];
}

// ---------------- SGEMM: C[M,NC] = A[M,K] @ B[K,NC] (+bias, relu) ----------------
#define BM 128
#define BN 64
#define BK 16
#define TM 8
#define TN 4

__global__ __launch_bounds__(256) void k_sgemm(
    const float* __restrict__ A, const float* __restrict__ B,
    const float* __restrict__ bias, float* __restrict__ C,
    int M, int K, int NC, int do_relu)
{
    __shared__ float As[BK][BM + 4];   // +4 keeps rows 16B-aligned, kills store conflicts
    __shared__ float Bs[BK][BN];

    int tid = threadIdx.x;
    int tx = tid & 15;        // 0..15 -> 64 cols (TN=4)
    int ty = tid >> 4;        // 0..15 -> 128 rows (TM=8)
    int rowBase = blockIdx.x * BM;
    int colBase = blockIdx.y * BN;

    float acc[TM][TN];
    #pragma unroll
    for (int i = 0; i < TM; i++)
        #pragma unroll
        for (int j = 0; j < TN; j++) acc[i][j] = 0.0f;

    for (int k0 = 0; k0 < K; k0 += BK) {
        // load A tile (BM x BK) as float4 along K, store transposed
        #pragma unroll
        for (int l0 = 0; l0 < 2; l0++) {
            int l = tid + l0 * 256;          // 0..511
            int ar = l >> 2;                 // 0..127
            int aq = l & 3;                  // 0..3 (k quad)
            int grow = rowBase + ar;
            float4 v = make_float4(0.f, 0.f, 0.f, 0.f);
            if (grow < M)
                v = *(const float4*)&A[(size_t)grow * K + k0 + aq * 4];
            As[aq * 4 + 0][ar] = v.x;
            As[aq * 4 + 1][ar] = v.y;
            As[aq * 4 + 2][ar] = v.z;
            As[aq * 4 + 3][ar] = v.w;
        }
        // load B tile (BK x BN): 256 float4s, one per thread
        {
            int br = tid >> 4;               // k row 0..15
            int bq = tid & 15;               // col quad 0..15
            float4 v = *(const float4*)&B[(size_t)(k0 + br) * NC + colBase + bq * 4];
            *(float4*)&Bs[br][bq * 4] = v;
        }
        __syncthreads();

        #pragma unroll
        for (int k = 0; k < BK; k++) {
            float a[TM], b[TN];
            #pragma unroll
            for (int i = 0; i < TM; i += 4) {
                float4 v = *(const float4*)&As[k][ty * TM + i];
                a[i] = v.x; a[i + 1] = v.y; a[i + 2] = v.z; a[i + 3] = v.w;
            }
            {
                float4 v = *(const float4*)&Bs[k][tx * TN];
                b[0] = v.x; b[1] = v.y; b[2] = v.z; b[3] = v.w;
            }
            #pragma unroll
            for (int i = 0; i < TM; i++)
                #pragma unroll
                for (int j = 0; j < TN; j++)
                    acc[i][j] = fmaf(a[i], b[j], acc[i][j]);
        }
        __syncthreads();
    }

    int gc = colBase + tx * TN;
    float bs[TN];
    #pragma unroll
    for (int j = 0; j < TN; j++) bs[j] = bias ? bias[gc + j] : 0.0f;

    #pragma unroll
    for (int i = 0; i < TM; i++) {
        int gr = rowBase + ty * TM + i;
        if (gr < M) {
            float4 v;
            float r0 = acc[i][0] + bs[0];
            float r1 = acc[i][1] + bs[1];
            float r2 = acc[i][2] + bs[2];
            float r3 = acc[i][3] + bs[3];
            if (do_relu) {
                r0 = fmaxf(r0, 0.f); r1 = fmaxf(r1, 0.f);
                r2 = fmaxf(r2, 0.f); r3 = fmaxf(r3, 0.f);
            }
            v.x = r0; v.y = r1; v.z = r2; v.w = r3;
            *(float4*)&C[(size_t)gr * NC + gc] = v;
        }
    }
}

// ---------------- per-layer aggregation + bias + BN + relu + residual ----------------
// one block (64 threads, float4 columns) per node
__global__ __launch_bounds__(64) void k_agg(
    const float* __restrict__ m, const float* __restrict__ h_in,
    float* __restrict__ h_out,
    const float* __restrict__ gb, const float* __restrict__ bng,
    const float* __restrict__ bnb, const float* __restrict__ bnm,
    const float* __restrict__ bnv)
{
    int node = blockIdx.x;
    int c4 = threadIdx.x;                    // 0..63
    const float4* m4 = (const float4*)m;

    int beg = g_rowptr[node];
    int end = g_rowptr[node + 1];
    float di = g_dinv[node];
    float sn = di * di;

    float4 mm = m4[node * H4 + c4];
    float4 acc = make_float4(mm.x * sn, mm.y * sn, mm.z * sn, mm.w * sn);

    for (int e = beg; e < end; e++) {
        int s = g_colidx[e];
        float w = g_ew[e];
        float4 v = m4[s * H4 + c4];
        acc.x = fmaf(v.x, w, acc.x);
        acc.y = fmaf(v.y, w, acc.y);
        acc.z = fmaf(v.z, w, acc.z);
        acc.w = fmaf(v.w, w, acc.w);
    }

    float4 b  = ((const float4*)gb)[c4];
    float4 ga = ((const float4*)bng)[c4];
    float4 be = ((const float4*)bnb)[c4];
    float4 mu = ((const float4*)bnm)[c4];
    float4 va = ((const float4*)bnv)[c4];
    float4 hi = ((const float4*)h_in)[node * H4 + c4];

    float4 o;
    o.x = fmaxf((acc.x + b.x - mu.x) * rsqrtf(va.x + 1e-5f) * ga.x + be.x, 0.f) + hi.x;
    o.y = fmaxf((acc.y + b.y - mu.y) * rsqrtf(va.y + 1e-5f) * ga.y + be.y, 0.f) + hi.y;
    o.z = fmaxf((acc.z + b.z - mu.z) * rsqrtf(va.z + 1e-5f) * ga.z + be.z, 0.f) + hi.z;
    o.w = fmaxf((acc.w + b.w - mu.w) * rsqrtf(va.w + 1e-5f) * ga.w + be.w, 0.f) + hi.w;
    ((float4*)h_out)[node * H4 + c4] = o;
}

// ---------------- global mean pool per graph (batch_idx is sorted) ----------------
__device__ __forceinline__ int lbound(const int* __restrict__ a, int n, int key)
{
    int lo = 0, hi = n;
    while (lo < hi) {
        int mid = (lo + hi) >> 1;
        if (a[mid] < key) lo = mid + 1; else hi = mid;
    }
    return lo;
}

__global__ __launch_bounds__(256) void k_pool(const float* __restrict__ h,
                                              const int* __restrict__ batch)
{
    int g = blockIdx.x;
    int c = threadIdx.x;
    int s = lbound(batch, Nn, g);
    int e = lbound(batch, Nn, g + 1);
    float acc = 0.0f;
    for (int n = s; n < e; n++) acc += h[(size_t)n * HH + c];
    float cnt = (float)(e - s);
    g_pool[g * HH + c] = acc / fmaxf(cnt, 1.0f);
}

// ---------------- property-head MLPs ----------------
__global__ __launch_bounds__(128) void k_heads(
    const float* __restrict__ h1W, const float* __restrict__ h1b,
    const float* __restrict__ h2W, const float* __restrict__ h2b,
    const float* __restrict__ h3W, const float* __restrict__ h3b,
    float* __restrict__ out)
{
    int g = blockIdx.x;
    int p = blockIdx.y;
    __shared__ float gs[HH];
    __shared__ float z1[128];
    __shared__ float z2[64];
    int t = threadIdx.x;

    gs[t] = g_pool[g * HH + t];
    gs[t + 128] = g_pool[g * HH + t + 128];
    __syncthreads();

    {   // layer 1: 256 -> 128
        const float* W1 = h1W + (size_t)p * HH * 128;
        float acc = h1b[p * 128 + t];
        #pragma unroll 8
        for (int k = 0; k < HH; k++) acc = fmaf(gs[k], W1[k * 128 + t], acc);
        z1[t] = fmaxf(acc, 0.0f);
    }
    __syncthreads();

    if (t < 64) {   // layer 2: 128 -> 64
        const float* W2 = h2W + (size_t)p * 128 * 64;
        float acc = h2b[p * 64 + t];
        #pragma unroll 8
        for (int k = 0; k < 128; k++) acc = fmaf(z1[k], W2[k * 64 + t], acc);
        z2[t] = fmaxf(acc, 0.0f);
    }
    __syncthreads();

    if (t < 32) {   // layer 3: 64 -> 1
        const float* W3 = h3W + p * 64;
        float a3 = z2[t] * W3[t] + z2[t + 32] * W3[t + 32];
        #pragma unroll
        for (int o = 16; o > 0; o >>= 1) a3 += __shfl_down_sync(0xffffffffu, a3, o);
        if (t == 0) out[g * PP + p] = a3 + h3b[p];
    }
}

// ---------------- launch ----------------
extern "C" void kernel_launch(void* const* d_in, const int* in_sizes, int n_in,
                              void* d_out, int out_size)
{
    const float* x     = (const float*)d_in[0];
    const int*   ei    = (const int*)d_in[1];
    const int*   batch = (const int*)d_in[2];
    const float* embW  = (const float*)d_in[3];
    const float* embb  = (const float*)d_in[4];
    const float* gcnW  = (const float*)d_in[5];
    const float* gcnb  = (const float*)d_in[6];
    const float* bng   = (const float*)d_in[7];
    const float* bnb   = (const float*)d_in[8];
    const float* bnm   = (const float*)d_in[9];
    const float* bnv   = (const float*)d_in[10];
    const float* h1W   = (const float*)d_in[11];
    const float* h1b   = (const float*)d_in[12];
    const float* h2W   = (const float*)d_in[13];
    const float* h2b   = (const float*)d_in[14];
    const float* h3W   = (const float*)d_in[15];
    const float* h3b   = (const float*)d_in[16];
    float* out = (float*)d_out;

    void *pA_, *pB_, *pM_;
    cudaGetSymbolAddress(&pA_, g_hA);
    cudaGetSymbolAddress(&pB_, g_hB);
    cudaGetSymbolAddress(&pM_, g_m);
    float* hA = (float*)pA_;
    float* hB = (float*)pB_;
    float* m  = (float*)pM_;

    // graph preprocessing (CSR by dst)
    k_zero<<<(Nn + 255) / 256, 256>>>();
    k_count<<<(Ee + 255) / 256, 256>>>(ei);
    k_dinv<<<(Nn + 255) / 256, 256>>>();
    k_scan<<<1, 1024>>>();
    k_fill<<<(Ee + 255) / 256, 256>>>(ei);

    dim3 ggrid((Nn + BM - 1) / BM, HH / BN);

    // embedding: h = relu(x @ embW + embb)
    k_sgemm<<<ggrid, 256>>>(x, embW, embb, hA, Nn, ND, HH, 1);

    // 4 GCN layers, ping-pong hA/hB
    for (int i = 0; i < LL; i++) {
        float* hin  = (i & 1) ? hB : hA;
        float* hout = (i & 1) ? hA : hB;
        k_sgemm<<<ggrid, 256>>>(hin, gcnW + (size_t)i * HH * HH, nullptr, m, Nn, HH, HH, 0);
        k_agg<<<Nn, 64>>>(m, hin, hout,
                          gcnb + i * HH, bng + i * HH, bnb + i * HH,
                          bnm + i * HH, bnv + i * HH);
    }
    // after layer 3 the result is in hA
    k_pool<<<Gg, 256>>>(hA, batch);
    k_heads<<<dim3(Gg, PP), 128>>>(h1W, h1b, h2W, h2b, h3W, h3b, out);
}

// round 2
// speedup vs baseline: 1.2226x; 1.2226x over previous
#include <cuda_runtime.h>
#include <cuda_bf16.h>
#include <math.h>
#include <stdint.h>

// Problem constants
#define Nn 50000
#define Ee 800000
#define Gg 1000
#define ND 128
#define HH 256
#define LL 4
#define PP 3
#define H4 (HH/4)

// ---------------- static scratch (no allocations allowed) ----------------
__device__ float g_hA[Nn * HH];
__device__ float g_hB[Nn * HH];
__device__ float g_m[Nn * HH];
__device__ int   g_cnt[Nn];
__device__ int   g_fill[Nn];
__device__ float g_dinv[Nn];
__device__ int   g_rowptr[Nn + 1];
__device__ int   g_colidx[Ee];
__device__ float g_ew[Ee];
__device__ float g_pool[Gg * HH];

// ---------------- graph preprocessing ----------------
__global__ void k_count(const int* __restrict__ ei)
{
    int e = blockIdx.x * blockDim.x + threadIdx.x;
    if (e < Ee) atomicAdd(&g_cnt[ei[Ee + e]], 1);
}

// one-pass block scan: 1024 threads, each owns a contiguous chunk.
// fuses dinv computation. Two reads of g_cnt (cheap) to avoid a 49-reg array.
#define SCAN_CH 49   // ceil(50000/1024)
__global__ __launch_bounds__(1024) void k_scan()
{
    __shared__ int wsum[32];
    int t = threadIdx.x;
    int lane = t & 31, wrp = t >> 5;
    int base = t * SCAN_CH;

    int s = 0;
    #pragma unroll 7
    for (int i = 0; i < SCAN_CH; i++) {
        int idx = base + i;
        if (idx < Nn) {
            int c = g_cnt[idx];
            g_dinv[idx] = rsqrtf(1.0f + (float)c);
            s += c;
        }
    }
    // warp inclusive scan of per-thread totals
    int ps = s;
    #pragma unroll
    for (int d = 1; d < 32; d <<= 1) {
        int x = __shfl_up_sync(0xffffffffu, ps, d);
        if (lane >= d) ps += x;
    }
    if (lane == 31) wsum[wrp] = ps;
    __syncthreads();
    if (wrp == 0) {
        int x = wsum[lane];
        #pragma unroll
        for (int d = 1; d < 32; d <<= 1) {
            int y = __shfl_up_sync(0xffffffffu, x, d);
            if (lane >= d) x += y;
        }
        wsum[lane] = x;
    }
    __syncthreads();
    int off = ps - s + (wrp ? wsum[wrp - 1] : 0);   // exclusive prefix of this thread

    #pragma unroll 7
    for (int i = 0; i < SCAN_CH; i++) {
        int idx = base + i;
        if (idx < Nn) {
            g_rowptr[idx] = off;
            off += g_cnt[idx];
        }
    }
    if (t == 0) g_rowptr[Nn] = Ee;
}

__global__ void k_fill(const int* __restrict__ ei)
{
    int e = blockIdx.x * blockDim.x + threadIdx.x;
    if (e >= Ee) return;
    int s = ei[e];
    int d = ei[Ee + e];
    int pos = g_rowptr[d] + atomicAdd(&g_fill[d], 1);
    g_colidx[pos] = s;
    g_ew[pos] = g_dinv[s] * g_dinv[d];
}

// ---------------- TF32 tensor-core GEMM ----------------
// C[M,256] = A[M,K] @ B[K,256] (+bias, relu). K % 32 == 0.
// Block tile 128x128, 8 warps (2 m x 4 n), warp tile 64x32,
// mma.sync.aligned.m16n8k8.row.col.f32.tf32.tf32.f32
#define BM 128
#define BN 128
#define BKK 32
#define GNC 256

__device__ __forceinline__ uint32_t f2tf32(float x)
{
    uint32_t r;
    asm("cvt.rna.tf32.f32 %0, %1;" : "=r"(r) : "f"(x));
    return r;
}

__global__ __launch_bounds__(256) void k_mma(
    const float* __restrict__ A, const float* __restrict__ B,
    const float* __restrict__ bias, float* __restrict__ C,
    int M, int K, int do_relu)
{
    __shared__ float As[BKK][BM + 4];   // stride 132 words: banks (4k+m)%32 conflict-free
    __shared__ float Bs[BKK][BN + 4];

    int tid = threadIdx.x;
    int wid = tid >> 5, lane = tid & 31;
    int wm = wid & 1;            // 0..1 -> 64-row slab
    int wn = wid >> 1;           // 0..3 -> 32-col slab
    int g = lane >> 2;           // 0..7
    int q = lane & 3;            // 0..3
    int rowBase = blockIdx.x * BM;
    int colBase = blockIdx.y * BN;

    float c[4][4][4];
    #pragma unroll
    for (int i = 0; i < 4; i++)
        #pragma unroll
        for (int j = 0; j < 4; j++)
            #pragma unroll
            for (int r = 0; r < 4; r++) c[i][j][r] = 0.0f;

    for (int k0 = 0; k0 < K; k0 += BKK) {
        // A tile: 128 rows x 32 k. 1024 float4 / 256 threads = 4 each.
        #pragma unroll
        for (int l = 0; l < 4; l++) {
            int j = tid + 256 * l;
            int row = j >> 3;            // 8 float4 per row
            int c4 = j & 7;
            int grow = rowBase + row;
            float4 v = make_float4(0.f, 0.f, 0.f, 0.f);
            if (grow < M)
                v = *(const float4*)&A[(size_t)grow * K + k0 + c4 * 4];
            int kc = c4 * 4;
            As[kc + 0][row] = __uint_as_float(f2tf32(v.x));
            As[kc + 1][row] = __uint_as_float(f2tf32(v.y));
            As[kc + 2][row] = __uint_as_float(f2tf32(v.z));
            As[kc + 3][row] = __uint_as_float(f2tf32(v.w));
        }
        // B tile: 32 k x 128 cols. 1024 float4 / 256 threads = 4 each.
        #pragma unroll
        for (int l = 0; l < 4; l++) {
            int j = tid + 256 * l;
            int row = j >> 5;            // 32 float4 per row
            int c4 = j & 31;
            float4 v = *(const float4*)&B[(size_t)(k0 + row) * GNC + colBase + c4 * 4];
            float4 w;
            w.x = __uint_as_float(f2tf32(v.x));
            w.y = __uint_as_float(f2tf32(v.y));
            w.z = __uint_as_float(f2tf32(v.z));
            w.w = __uint_as_float(f2tf32(v.w));
            *(float4*)&Bs[row][c4 * 4] = w;
        }
        __syncthreads();

        #pragma unroll
        for (int ks = 0; ks < 4; ks++) {
            int kk = ks * 8;
            uint32_t a[4][4], b[4][2];
            #pragma unroll
            for (int mt = 0; mt < 4; mt++) {
                int m = wm * 64 + mt * 16;
                a[mt][0] = __float_as_uint(As[kk + q][m + g]);
                a[mt][1] = __float_as_uint(As[kk + q][m + g + 8]);
                a[mt][2] = __float_as_uint(As[kk + q + 4][m + g]);
                a[mt][3] = __float_as_uint(As[kk + q + 4][m + g + 8]);
            }
            #pragma unroll
            for (int nt = 0; nt < 4; nt++) {
                int n = wn * 32 + nt * 8;
                b[nt][0] = __float_as_uint(Bs[kk + q][n + g]);
                b[nt][1] = __float_as_uint(Bs[kk + q + 4][n + g]);
            }
            #pragma unroll
            for (int mt = 0; mt < 4; mt++)
                #pragma unroll
                for (int nt = 0; nt < 4; nt++) {
                    asm volatile(
                        "mma.sync.aligned.m16n8k8.row.col.f32.tf32.tf32.f32 "
                        "{%0,%1,%2,%3}, {%4,%5,%6,%7}, {%8,%9}, {%0,%1,%2,%3};\n"
                        : "+f"(c[mt][nt][0]), "+f"(c[mt][nt][1]),
                          "+f"(c[mt][nt][2]), "+f"(c[mt][nt][3])
                        : "r"(a[mt][0]), "r"(a[mt][1]), "r"(a[mt][2]), "r"(a[mt][3]),
                          "r"(b[nt][0]), "r"(b[nt][1]));
                }
        }
        __syncthreads();
    }

    // epilogue: fragment (g = row-in-16, q -> col pair)
    #pragma unroll
    for (int nt = 0; nt < 4; nt++) {
        int col = colBase + wn * 32 + nt * 8 + 2 * q;
        float b0 = 0.f, b1 = 0.f;
        if (bias) { b0 = bias[col]; b1 = bias[col + 1]; }
        #pragma unroll
        for (int mt = 0; mt < 4; mt++) {
            int r0 = rowBase + wm * 64 + mt * 16 + g;
            float v0 = c[mt][nt][0] + b0;
            float v1 = c[mt][nt][1] + b1;
            float v2 = c[mt][nt][2] + b0;
            float v3 = c[mt][nt][3] + b1;
            if (do_relu) {
                v0 = fmaxf(v0, 0.f); v1 = fmaxf(v1, 0.f);
                v2 = fmaxf(v2, 0.f); v3 = fmaxf(v3, 0.f);
            }
            if (r0 < M)      *(float2*)&C[(size_t)r0 * GNC + col]       = make_float2(v0, v1);
            if (r0 + 8 < M)  *(float2*)&C[(size_t)(r0 + 8) * GNC + col] = make_float2(v2, v3);
        }
    }
}

// ---------------- per-layer aggregation + bias + BN + relu + residual ----------------
__global__ __launch_bounds__(64) void k_agg(
    const float* __restrict__ m, const float* __restrict__ h_in,
    float* __restrict__ h_out,
    const float* __restrict__ gb, const float* __restrict__ bng,
    const float* __restrict__ bnb, const float* __restrict__ bnm,
    const float* __restrict__ bnv)
{
    int node = blockIdx.x;
    int c4 = threadIdx.x;                    // 0..63
    const float4* m4 = (const float4*)m;

    int beg = g_rowptr[node];
    int end = g_rowptr[node + 1];
    float di = g_dinv[node];
    float sn = di * di;

    float4 mm = m4[node * H4 + c4];
    float4 acc = make_float4(mm.x * sn, mm.y * sn, mm.z * sn, mm.w * sn);

    for (int e = beg; e < end; e++) {
        int s = g_colidx[e];
        float w = g_ew[e];
        float4 v = m4[s * H4 + c4];
        acc.x = fmaf(v.x, w, acc.x);
        acc.y = fmaf(v.y, w, acc.y);
        acc.z = fmaf(v.z, w, acc.z);
        acc.w = fmaf(v.w, w, acc.w);
    }

    float4 b  = ((const float4*)gb)[c4];
    float4 ga = ((const float4*)bng)[c4];
    float4 be = ((const float4*)bnb)[c4];
    float4 mu = ((const float4*)bnm)[c4];
    float4 va = ((const float4*)bnv)[c4];
    float4 hi = ((const float4*)h_in)[node * H4 + c4];

    float4 o;
    o.x = fmaxf((acc.x + b.x - mu.x) * rsqrtf(va.x + 1e-5f) * ga.x + be.x, 0.f) + hi.x;
    o.y = fmaxf((acc.y + b.y - mu.y) * rsqrtf(va.y + 1e-5f) * ga.y + be.y, 0.f) + hi.y;
    o.z = fmaxf((acc.z + b.z - mu.z) * rsqrtf(va.z + 1e-5f) * ga.z + be.z, 0.f) + hi.z;
    o.w = fmaxf((acc.w + b.w - mu.w) * rsqrtf(va.w + 1e-5f) * ga.w + be.w, 0.f) + hi.w;
    ((float4*)h_out)[node * H4 + c4] = o;
}

// ---------------- global mean pool per graph (batch_idx is sorted) ----------------
__device__ __forceinline__ int lbound(const int* __restrict__ a, int n, int key)
{
    int lo = 0, hi = n;
    while (lo < hi) {
        int mid = (lo + hi) >> 1;
        if (a[mid] < key) lo = mid + 1; else hi = mid;
    }
    return lo;
}

__global__ __launch_bounds__(256) void k_pool(const float* __restrict__ h,
                                              const int* __restrict__ batch)
{
    int g = blockIdx.x;
    int c = threadIdx.x;
    int s = lbound(batch, Nn, g);
    int e = lbound(batch, Nn, g + 1);
    float acc = 0.0f;
    for (int n = s; n < e; n++) acc += h[(size_t)n * HH + c];
    float cnt = (float)(e - s);
    g_pool[g * HH + c] = acc / fmaxf(cnt, 1.0f);
}

// ---------------- property-head MLPs ----------------
__global__ __launch_bounds__(128) void k_heads(
    const float* __restrict__ h1W, const float* __restrict__ h1b,
    const float* __restrict__ h2W, const float* __restrict__ h2b,
    const float* __restrict__ h3W, const float* __restrict__ h3b,
    float* __restrict__ out)
{
    int g = blockIdx.x;
    int p = blockIdx.y;
    __shared__ float gs[HH];
    __shared__ float z1[128];
    __shared__ float z2[64];
    int t = threadIdx.x;

    gs[t] = g_pool[g * HH + t];
    gs[t + 128] = g_pool[g * HH + t + 128];
    __syncthreads();

    {   // layer 1: 256 -> 128
        const float* W1 = h1W + (size_t)p * HH * 128;
        float acc = h1b[p * 128 + t];
        #pragma unroll 8
        for (int k = 0; k < HH; k++) acc = fmaf(gs[k], W1[k * 128 + t], acc);
        z1[t] = fmaxf(acc, 0.0f);
    }
    __syncthreads();

    if (t < 64) {   // layer 2: 128 -> 64
        const float* W2 = h2W + (size_t)p * 128 * 64;
        float acc = h2b[p * 64 + t];
        #pragma unroll 8
        for (int k = 0; k < 128; k++) acc = fmaf(z1[k], W2[k * 64 + t], acc);
        z2[t] = fmaxf(acc, 0.0f);
    }
    __syncthreads();

    if (t < 32) {   // layer 3: 64 -> 1
        const float* W3 = h3W + p * 64;
        float a3 = z2[t] * W3[t] + z2[t + 32] * W3[t + 32];
        #pragma unroll
        for (int o = 16; o > 0; o >>= 1) a3 += __shfl_down_sync(0xffffffffu, a3, o);
        if (t == 0) out[g * PP + p] = a3 + h3b[p];
    }
}

// ---------------- launch ----------------
extern "C" void kernel_launch(void* const* d_in, const int* in_sizes, int n_in,
                              void* d_out, int out_size)
{
    const float* x     = (const float*)d_in[0];
    const int*   ei    = (const int*)d_in[1];
    const int*   batch = (const int*)d_in[2];
    const float* embW  = (const float*)d_in[3];
    const float* embb  = (const float*)d_in[4];
    const float* gcnW  = (const float*)d_in[5];
    const float* gcnb  = (const float*)d_in[6];
    const float* bng   = (const float*)d_in[7];
    const float* bnb   = (const float*)d_in[8];
    const float* bnm   = (const float*)d_in[9];
    const float* bnv   = (const float*)d_in[10];
    const float* h1W   = (const float*)d_in[11];
    const float* h1b   = (const float*)d_in[12];
    const float* h2W   = (const float*)d_in[13];
    const float* h2b   = (const float*)d_in[14];
    const float* h3W   = (const float*)d_in[15];
    const float* h3b   = (const float*)d_in[16];
    float* out = (float*)d_out;

    void *pA_, *pB_, *pM_, *pCnt_, *pFill_;
    cudaGetSymbolAddress(&pA_, g_hA);
    cudaGetSymbolAddress(&pB_, g_hB);
    cudaGetSymbolAddress(&pM_, g_m);
    cudaGetSymbolAddress(&pCnt_, g_cnt);
    cudaGetSymbolAddress(&pFill_, g_fill);
    float* hA = (float*)pA_;
    float* hB = (float*)pB_;
    float* m  = (float*)pM_;

    // graph preprocessing (CSR by dst)
    cudaMemsetAsync(pCnt_, 0, Nn * sizeof(int));
    cudaMemsetAsync(pFill_, 0, Nn * sizeof(int));
    k_count<<<(Ee + 255) / 256, 256>>>(ei);
    k_scan<<<1, 1024>>>();
    k_fill<<<(Ee + 255) / 256, 256>>>(ei);

    dim3 ggrid((Nn + BM - 1) / BM, GNC / BN);

    // embedding: h = relu(x @ embW + embb)
    k_mma<<<ggrid, 256>>>(x, embW, embb, hA, Nn, ND, 1);

    // 4 GCN layers, ping-pong hA/hB
    for (int i = 0; i < LL; i++) {
        float* hin  = (i & 1) ? hB : hA;
        float* hout = (i & 1) ? hA : hB;
        k_mma<<<ggrid, 256>>>(hin, gcnW + (size_t)i * HH * HH, nullptr, m, Nn, HH, 0);
        k_agg<<<Nn, 64>>>(m, hin, hout,
                          gcnb + i * HH, bng + i * HH, bnb + i * HH,
                          bnm + i * HH, bnv + i * HH);
    }
    // after layer 3 the result is in hA
    k_pool<<<Gg, 256>>>(hA, batch);
    k_heads<<<dim3(Gg, PP), 128>>>(h1W, h1b, h2W, h2b, h3W, h3b, out);
}

// round 3
// speedup vs baseline: 2.0037x; 1.6389x over previous
#include <cuda_runtime.h>
#include <cuda_fp16.h>
#include <math.h>
#include <stdint.h>

// Problem constants
#define Nn 50000
#define Ee 800000
#define Gg 1000
#define ND 128
#define HH 256
#define LL 4
#define PP 3

// ---------------- static scratch (no allocations allowed) ----------------
__device__ float  g_hA[Nn * HH];
__device__ float  g_hB[Nn * HH];
__device__ __half g_x16[Nn * ND];
__device__ __half g_h16[Nn * HH];
__device__ __half g_m16[Nn * HH];
__device__ __half g_embWT[HH * ND];          // [n][k] = emb_W[k][n]
__device__ __half g_gcnWT[LL * HH * HH];     // [l][n][k] = gcn_W[l][k][n]
__device__ float  g_bnS[LL * HH];
__device__ float  g_bnT[LL * HH];
__device__ int    g_cnt[Nn];
__device__ int    g_fill[Nn];
__device__ float  g_dinv[Nn];
__device__ int    g_rowptr[Nn + 1];
__device__ int    g_colidx[Ee];
__device__ float  g_ew[Ee];
__device__ float  g_pool[Gg * HH];

// ---------------- graph preprocessing ----------------
__global__ void k_count(const int* __restrict__ ei)
{
    int e = blockIdx.x * blockDim.x + threadIdx.x;
    if (e < Ee) atomicAdd(&g_cnt[ei[Ee + e]], 1);
}

#define SCAN_CH 49   // ceil(50000/1024)
__global__ __launch_bounds__(1024) void k_scan()
{
    __shared__ int wsum[32];
    int t = threadIdx.x;
    int lane = t & 31, wrp = t >> 5;
    int base = t * SCAN_CH;

    int s = 0;
    #pragma unroll 7
    for (int i = 0; i < SCAN_CH; i++) {
        int idx = base + i;
        if (idx < Nn) {
            int c = g_cnt[idx];
            g_dinv[idx] = rsqrtf(1.0f + (float)c);
            s += c;
        }
    }
    int ps = s;
    #pragma unroll
    for (int d = 1; d < 32; d <<= 1) {
        int x = __shfl_up_sync(0xffffffffu, ps, d);
        if (lane >= d) ps += x;
    }
    if (lane == 31) wsum[wrp] = ps;
    __syncthreads();
    if (wrp == 0) {
        int x = wsum[lane];
        #pragma unroll
        for (int d = 1; d < 32; d <<= 1) {
            int y = __shfl_up_sync(0xffffffffu, x, d);
            if (lane >= d) x += y;
        }
        wsum[lane] = x;
    }
    __syncthreads();
    int off = ps - s + (wrp ? wsum[wrp - 1] : 0);

    #pragma unroll 7
    for (int i = 0; i < SCAN_CH; i++) {
        int idx = base + i;
        if (idx < Nn) {
            g_rowptr[idx] = off;
            off += g_cnt[idx];
        }
    }
    if (t == 0) g_rowptr[Nn] = Ee;
}

__global__ void k_fill(const int* __restrict__ ei)
{
    int e = blockIdx.x * blockDim.x + threadIdx.x;
    if (e >= Ee) return;
    int s = ei[e];
    int d = ei[Ee + e];
    int pos = g_rowptr[d] + atomicAdd(&g_fill[d], 1);
    g_colidx[pos] = s;
    g_ew[pos] = g_dinv[s] * g_dinv[d];
}

// ---------------- prep: convert x to fp16 (vectorized) ----------------
__global__ __launch_bounds__(256) void k_prep_x(const float* __restrict__ x)
{
    int i4 = blockIdx.x * blockDim.x + threadIdx.x;   // float4 index
    if (i4 >= Nn * ND / 4) return;
    float4 v = ((const float4*)x)[i4];
    __half2 a = __floats2half2_rn(v.x, v.y);
    __half2 b = __floats2half2_rn(v.z, v.w);
    uint2 o;
    o.x = *(uint32_t*)&a;
    o.y = *(uint32_t*)&b;
    ((uint2*)g_x16)[i4] = o;
}

// ---------------- prep: transpose+convert weights, fold BN ----------------
#define WELEMS (HH*ND + LL*HH*HH)
__global__ __launch_bounds__(256) void k_prep_w(
    const float* __restrict__ embW, const float* __restrict__ gcnW,
    const float* __restrict__ gcnb, const float* __restrict__ bng,
    const float* __restrict__ bnb, const float* __restrict__ bnm,
    const float* __restrict__ bnv)
{
    int t = blockIdx.x * blockDim.x + threadIdx.x;
    if (t < HH * ND) {
        int n = t / ND, k = t % ND;
        g_embWT[t] = __float2half_rn(embW[k * HH + n]);
    } else if (t < WELEMS) {
        int t2 = t - HH * ND;
        int l = t2 >> 16;
        int r = t2 & 65535;
        int n = r >> 8, k = r & 255;
        g_gcnWT[t2] = __float2half_rn(gcnW[l * HH * HH + k * HH + n]);
    } else if (t < WELEMS + LL * HH) {
        int i = t - WELEMS;   // l*HH + c
        float S = bng[i] * rsqrtf(bnv[i] + 1e-5f);
        g_bnS[i] = S;
        g_bnT[i] = (gcnb[i] - bnm[i]) * S + bnb[i];
    }
}

// ---------------- fp16 tensor-core GEMM with cp.async pipeline ----------------
// C[M,256] = A[M,K] @ W[K,256], W given transposed (BT[n][k], fp16).
// Block 128x128, 8 warps (2x4), warp tile 64x32, mma m16n8k16 f16->f32.
__device__ __forceinline__ void cpa16(uint32_t dst, const void* src, int sz)
{
    asm volatile("cp.async.cg.shared.global [%0], [%1], 16, %2;\n"
                 :: "r"(dst), "l"(src), "r"(sz));
}
#define CP_COMMIT() asm volatile("cp.async.commit_group;\n" ::)
#define CP_WAIT(N)  asm volatile("cp.async.wait_group %0;\n" :: "n"(N))

template<int K>
__global__ __launch_bounds__(256) void k_hgemm(
    const __half* __restrict__ A, const __half* __restrict__ BT,
    const float* __restrict__ bias, float* __restrict__ C32,
    __half* __restrict__ C16, int M, int do_relu)
{
    constexpr int KT = K / 32;
    __shared__ __align__(16) __half As[2][128][40];
    __shared__ __align__(16) __half Bs[2][128][40];

    int tid = threadIdx.x;
    int wid = tid >> 5, lane = tid & 31;
    int wm = wid & 1;
    int wn = wid >> 1;
    int g = lane >> 2;
    int q = lane & 3;
    int rowBase = blockIdx.x * 128;
    int colBase = blockIdx.y * 128;

    uint32_t sA = (uint32_t)__cvta_generic_to_shared(&As[0][0][0]);
    uint32_t sB = (uint32_t)__cvta_generic_to_shared(&Bs[0][0][0]);
    const int STAGE = 128 * 80;   // bytes per buffer

    float c[4][4][4];
    #pragma unroll
    for (int i = 0; i < 4; i++)
        #pragma unroll
        for (int j = 0; j < 4; j++)
            #pragma unroll
            for (int r = 0; r < 4; r++) c[i][j][r] = 0.0f;

    int ldrow = tid >> 2;       // 0..63
    int ldc = tid & 3;          // chunk 0..3

    // stage(kt, buf)
    auto stage = [&](int kt, int buf) {
        #pragma unroll
        for (int l = 0; l < 2; l++) {
            int row = ldrow + l * 64;
            int ga = rowBase + row;
            const __half* srcA = A + (size_t)ga * K + kt * 32 + ldc * 8;
            cpa16(sA + buf * STAGE + row * 80 + ldc * 16, srcA, (ga < M) ? 16 : 0);
            const __half* srcB = BT + (size_t)(colBase + row) * K + kt * 32 + ldc * 8;
            cpa16(sB + buf * STAGE + row * 80 + ldc * 16, srcB, 16);
        }
    };

    stage(0, 0);
    CP_COMMIT();

    for (int kt = 0; kt < KT; kt++) {
        if (kt + 1 < KT) {
            stage(kt + 1, (kt + 1) & 1);
            CP_COMMIT();
            CP_WAIT(1);
        } else {
            CP_WAIT(0);
        }
        __syncthreads();
        int buf = kt & 1;

        #pragma unroll
        for (int ks = 0; ks < 32; ks += 16) {
            uint32_t a[4][4], b[4][2];
            #pragma unroll
            for (int mt = 0; mt < 4; mt++) {
                int m = wm * 64 + mt * 16;
                a[mt][0] = *(const uint32_t*)&As[buf][m + g][ks + 2 * q];
                a[mt][1] = *(const uint32_t*)&As[buf][m + g + 8][ks + 2 * q];
                a[mt][2] = *(const uint32_t*)&As[buf][m + g][ks + 2 * q + 8];
                a[mt][3] = *(const uint32_t*)&As[buf][m + g + 8][ks + 2 * q + 8];
            }
            #pragma unroll
            for (int nt = 0; nt < 4; nt++) {
                int n = wn * 32 + nt * 8 + g;
                b[nt][0] = *(const uint32_t*)&Bs[buf][n][ks + 2 * q];
                b[nt][1] = *(const uint32_t*)&Bs[buf][n][ks + 2 * q + 8];
            }
            #pragma unroll
            for (int mt = 0; mt < 4; mt++)
                #pragma unroll
                for (int nt = 0; nt < 4; nt++) {
                    asm volatile(
                        "mma.sync.aligned.m16n8k16.row.col.f32.f16.f16.f32 "
                        "{%0,%1,%2,%3}, {%4,%5,%6,%7}, {%8,%9}, {%0,%1,%2,%3};\n"
                        : "+f"(c[mt][nt][0]), "+f"(c[mt][nt][1]),
                          "+f"(c[mt][nt][2]), "+f"(c[mt][nt][3])
                        : "r"(a[mt][0]), "r"(a[mt][1]), "r"(a[mt][2]), "r"(a[mt][3]),
                          "r"(b[nt][0]), "r"(b[nt][1]));
                }
        }
        __syncthreads();
    }

    // epilogue
    #pragma unroll
    for (int nt = 0; nt < 4; nt++) {
        int col = colBase + wn * 32 + nt * 8 + 2 * q;
        float b0 = 0.f, b1 = 0.f;
        if (bias) { b0 = bias[col]; b1 = bias[col + 1]; }
        #pragma unroll
        for (int mt = 0; mt < 4; mt++) {
            int r0 = rowBase + wm * 64 + mt * 16 + g;
            float v0 = c[mt][nt][0] + b0;
            float v1 = c[mt][nt][1] + b1;
            float v2 = c[mt][nt][2] + b0;
            float v3 = c[mt][nt][3] + b1;
            if (do_relu) {
                v0 = fmaxf(v0, 0.f); v1 = fmaxf(v1, 0.f);
                v2 = fmaxf(v2, 0.f); v3 = fmaxf(v3, 0.f);
            }
            if (r0 < M) {
                if (C32) *(float2*)&C32[(size_t)r0 * HH + col] = make_float2(v0, v1);
                if (C16) {
                    __half2 h = __floats2half2_rn(v0, v1);
                    *(uint32_t*)&C16[(size_t)r0 * HH + col] = *(uint32_t*)&h;
                }
            }
            if (r0 + 8 < M) {
                if (C32) *(float2*)&C32[(size_t)(r0 + 8) * HH + col] = make_float2(v2, v3);
                if (C16) {
                    __half2 h = __floats2half2_rn(v2, v3);
                    *(uint32_t*)&C16[(size_t)(r0 + 8) * HH + col] = *(uint32_t*)&h;
                }
            }
        }
    }
}

// ---------------- aggregation: warp per node, fp16 gather, fp32 accum ----------------
__global__ __launch_bounds__(256) void k_agg(
    const __half* __restrict__ m16, const float* __restrict__ h_in,
    float* __restrict__ h_out, __half* __restrict__ h16_out,
    const float* __restrict__ S, const float* __restrict__ T)
{
    int wid = threadIdx.x >> 5;
    int l = threadIdx.x & 31;
    int node = blockIdx.x * 8 + wid;
    if (node >= Nn) return;

    const uint4* mv = (const uint4*)m16;   // 32 uint4 per row (256 halves)
    int beg = g_rowptr[node];
    int end = g_rowptr[node + 1];
    float di = g_dinv[node];
    float sn = di * di;

    float acc[8];
    {
        uint4 v = mv[(size_t)node * 32 + l];
        const __half2* h = (const __half2*)&v;
        #pragma unroll
        for (int j = 0; j < 4; j++) {
            float2 f = __half22float2(h[j]);
            acc[2 * j] = f.x * sn;
            acc[2 * j + 1] = f.y * sn;
        }
    }

    for (int e = beg; e < end; e++) {
        int s = __ldg(&g_colidx[e]);
        float w = __ldg(&g_ew[e]);
        uint4 v = mv[(size_t)s * 32 + l];
        const __half2* h = (const __half2*)&v;
        #pragma unroll
        for (int j = 0; j < 4; j++) {
            float2 f = __half22float2(h[j]);
            acc[2 * j] = fmaf(f.x, w, acc[2 * j]);
            acc[2 * j + 1] = fmaf(f.y, w, acc[2 * j + 1]);
        }
    }

    // epilogue: o = relu(acc*S + T) + h_in; write fp32 + fp16 copies
    float4 s0 = ((const float4*)S)[l * 2];
    float4 s1 = ((const float4*)S)[l * 2 + 1];
    float4 t0 = ((const float4*)T)[l * 2];
    float4 t1 = ((const float4*)T)[l * 2 + 1];
    float4 hi0 = ((const float4*)h_in)[(size_t)node * 64 + l * 2];
    float4 hi1 = ((const float4*)h_in)[(size_t)node * 64 + l * 2 + 1];

    float o[8];
    o[0] = fmaxf(fmaf(acc[0], s0.x, t0.x), 0.f) + hi0.x;
    o[1] = fmaxf(fmaf(acc[1], s0.y, t0.y), 0.f) + hi0.y;
    o[2] = fmaxf(fmaf(acc[2], s0.z, t0.z), 0.f) + hi0.z;
    o[3] = fmaxf(fmaf(acc[3], s0.w, t0.w), 0.f) + hi0.w;
    o[4] = fmaxf(fmaf(acc[4], s1.x, t1.x), 0.f) + hi1.x;
    o[5] = fmaxf(fmaf(acc[5], s1.y, t1.y), 0.f) + hi1.y;
    o[6] = fmaxf(fmaf(acc[6], s1.z, t1.z), 0.f) + hi1.z;
    o[7] = fmaxf(fmaf(acc[7], s1.w, t1.w), 0.f) + hi1.w;

    ((float4*)h_out)[(size_t)node * 64 + l * 2]     = make_float4(o[0], o[1], o[2], o[3]);
    ((float4*)h_out)[(size_t)node * 64 + l * 2 + 1] = make_float4(o[4], o[5], o[6], o[7]);

    __half2 p0 = __floats2half2_rn(o[0], o[1]);
    __half2 p1 = __floats2half2_rn(o[2], o[3]);
    __half2 p2 = __floats2half2_rn(o[4], o[5]);
    __half2 p3 = __floats2half2_rn(o[6], o[7]);
    uint4 pk;
    pk.x = *(uint32_t*)&p0; pk.y = *(uint32_t*)&p1;
    pk.z = *(uint32_t*)&p2; pk.w = *(uint32_t*)&p3;
    ((uint4*)h16_out)[(size_t)node * 32 + l] = pk;
}

// ---------------- global mean pool per graph (batch_idx is sorted) ----------------
__device__ __forceinline__ int lbound(const int* __restrict__ a, int n, int key)
{
    int lo = 0, hi = n;
    while (lo < hi) {
        int mid = (lo + hi) >> 1;
        if (a[mid] < key) lo = mid + 1; else hi = mid;
    }
    return lo;
}

__global__ __launch_bounds__(256) void k_pool(const float* __restrict__ h,
                                              const int* __restrict__ batch)
{
    int g = blockIdx.x;
    int c = threadIdx.x;
    int s = lbound(batch, Nn, g);
    int e = lbound(batch, Nn, g + 1);
    float acc = 0.0f;
    for (int n = s; n < e; n++) acc += h[(size_t)n * HH + c];
    float cnt = (float)(e - s);
    g_pool[g * HH + c] = acc / fmaxf(cnt, 1.0f);
}

// ---------------- property-head MLPs ----------------
__global__ __launch_bounds__(128) void k_heads(
    const float* __restrict__ h1W, const float* __restrict__ h1b,
    const float* __restrict__ h2W, const float* __restrict__ h2b,
    const float* __restrict__ h3W, const float* __restrict__ h3b,
    float* __restrict__ out)
{
    int g = blockIdx.x;
    int p = blockIdx.y;
    __shared__ float gs[HH];
    __shared__ float z1[128];
    __shared__ float z2[64];
    int t = threadIdx.x;

    gs[t] = g_pool[g * HH + t];
    gs[t + 128] = g_pool[g * HH + t + 128];
    __syncthreads();

    {
        const float* W1 = h1W + (size_t)p * HH * 128;
        float acc = h1b[p * 128 + t];
        #pragma unroll 8
        for (int k = 0; k < HH; k++) acc = fmaf(gs[k], W1[k * 128 + t], acc);
        z1[t] = fmaxf(acc, 0.0f);
    }
    __syncthreads();

    if (t < 64) {
        const float* W2 = h2W + (size_t)p * 128 * 64;
        float acc = h2b[p * 64 + t];
        #pragma unroll 8
        for (int k = 0; k < 128; k++) acc = fmaf(z1[k], W2[k * 64 + t], acc);
        z2[t] = fmaxf(acc, 0.0f);
    }
    __syncthreads();

    if (t < 32) {
        const float* W3 = h3W + p * 64;
        float a3 = z2[t] * W3[t] + z2[t + 32] * W3[t + 32];
        #pragma unroll
        for (int o = 16; o > 0; o >>= 1) a3 += __shfl_down_sync(0xffffffffu, a3, o);
        if (t == 0) out[g * PP + p] = a3 + h3b[p];
    }
}

// ---------------- launch ----------------
extern "C" void kernel_launch(void* const* d_in, const int* in_sizes, int n_in,
                              void* d_out, int out_size)
{
    const float* x     = (const float*)d_in[0];
    const int*   ei    = (const int*)d_in[1];
    const int*   batch = (const int*)d_in[2];
    const float* embW  = (const float*)d_in[3];
    const float* embb  = (const float*)d_in[4];
    const float* gcnW  = (const float*)d_in[5];
    const float* gcnb  = (const float*)d_in[6];
    const float* bng   = (const float*)d_in[7];
    const float* bnb   = (const float*)d_in[8];
    const float* bnm   = (const float*)d_in[9];
    const float* bnv   = (const float*)d_in[10];
    const float* h1W   = (const float*)d_in[11];
    const float* h1b   = (const float*)d_in[12];
    const float* h2W   = (const float*)d_in[13];
    const float* h2b   = (const float*)d_in[14];
    const float* h3W   = (const float*)d_in[15];
    const float* h3b   = (const float*)d_in[16];
    float* out = (float*)d_out;

    void *pA_, *pB_, *pX16_, *pH16_, *pM16_, *pEWT_, *pGWT_, *pS_, *pT_, *pCnt_, *pFill_;
    cudaGetSymbolAddress(&pA_, g_hA);
    cudaGetSymbolAddress(&pB_, g_hB);
    cudaGetSymbolAddress(&pX16_, g_x16);
    cudaGetSymbolAddress(&pH16_, g_h16);
    cudaGetSymbolAddress(&pM16_, g_m16);
    cudaGetSymbolAddress(&pEWT_, g_embWT);
    cudaGetSymbolAddress(&pGWT_, g_gcnWT);
    cudaGetSymbolAddress(&pS_, g_bnS);
    cudaGetSymbolAddress(&pT_, g_bnT);
    cudaGetSymbolAddress(&pCnt_, g_cnt);
    cudaGetSymbolAddress(&pFill_, g_fill);
    float*  hA  = (float*)pA_;
    float*  hB  = (float*)pB_;
    __half* x16 = (__half*)pX16_;
    __half* h16 = (__half*)pH16_;
    __half* m16 = (__half*)pM16_;
    __half* eWT = (__half*)pEWT_;
    __half* gWT = (__half*)pGWT_;
    float*  bnS = (float*)pS_;
    float*  bnT = (float*)pT_;

    // graph preprocessing (CSR by dst)
    cudaMemsetAsync(pCnt_, 0, Nn * sizeof(int));
    cudaMemsetAsync(pFill_, 0, Nn * sizeof(int));
    k_count<<<(Ee + 255) / 256, 256>>>(ei);
    k_scan<<<1, 1024>>>();
    k_fill<<<(Ee + 255) / 256, 256>>>(ei);

    // fp16 conversions / weight transpose / BN folding
    k_prep_x<<<(Nn * ND / 4 + 255) / 256, 256>>>(x);
    k_prep_w<<<(WELEMS + LL * HH + 255) / 256, 256>>>(embW, gcnW, gcnb, bng, bnb, bnm, bnv);

    dim3 ggrid((Nn + 127) / 128, 2);

    // embedding: h = relu(x @ embW + embb) -> fp32 hA + fp16 h16
    k_hgemm<ND><<<ggrid, 256>>>(x16, eWT, embb, hA, h16, Nn, 1);

    // 4 GCN layers
    for (int i = 0; i < LL; i++) {
        float* hin  = (i & 1) ? hB : hA;
        float* hout = (i & 1) ? hA : hB;
        k_hgemm<HH><<<ggrid, 256>>>(h16, gWT + (size_t)i * HH * HH, nullptr,
                                    nullptr, m16, Nn, 0);
        k_agg<<<(Nn + 7) / 8, 256>>>(m16, hin, hout, h16,
                                     bnS + i * HH, bnT + i * HH);
    }
    // after layer 3 the result is in hA
    k_pool<<<Gg, 256>>>(hA, batch);
    k_heads<<<dim3(Gg, PP), 128>>>(h1W, h1b, h2W, h2b, h3W, h3b, out);
}